// round 7
// baseline (speedup 1.0000x reference)
#include <cuda_runtime.h>
#include <math.h>

#define NB   32
#define RESO 256
#define KK   1024
#define EPSF 1e-6f
#define HALF_I (KK / 2)   // 512

// log2(e)^2 and ln(2)
#define LOG2E2  2.0813689810056077f
#define LN2     0.6931471805599453f

// Scratch (no allocations allowed).
// src: (sx, sy, |s|^2 * log2e^2, 0)
// trg: (tx', ty', |t'|^2, 0) with t' = t - eps
__device__ float4 g_src4[NB * KK];
__device__ float4 g_trg4[NB * KK];
__device__ double g_loss;
__device__ double g_vis;
__device__ unsigned int g_done;

__device__ __forceinline__ float sqrt_approx(float x) {
    float r; asm("sqrt.approx.f32 %0, %1;" : "=f"(r) : "f"(x)); return r;
}
__device__ __forceinline__ float ex2_approx(float x) {
    float r; asm("ex2.approx.f32 %0, %1;" : "=f"(r) : "f"(x)); return r;
}
__device__ __forceinline__ float lg2_approx(float x) {
    float r; asm("lg2.approx.f32 %0, %1;" : "=f"(r) : "f"(x)); return r;
}

// ---------------------------------------------------------------------------
// Kernel 1: bilinear sampling; emits packed float4 per point.
// ---------------------------------------------------------------------------
__global__ void sample_kernel(const float* __restrict__ src_flow,
                              const float* __restrict__ trg_flow,
                              const float* __restrict__ src_kp,
                              const float* __restrict__ trg_kp) {
    int tid = blockIdx.x * blockDim.x + threadIdx.x;
    if (tid == 0) { g_loss = 0.0; g_vis = 0.0; g_done = 0u; }
    if (tid >= 2 * NB * KK) return;

    int sel = tid >= NB * KK;          // 0 = src, 1 = trg
    int idx = sel ? (tid - NB * KK) : tid;
    const float* flow = sel ? trg_flow : src_flow;
    const float2 p = reinterpret_cast<const float2*>(sel ? trg_kp : src_kp)[idx];

    int   n = idx / KK;

    float x0f = floorf(p.x), y0f = floorf(p.y);
    int   x0  = (int)x0f,    y0  = (int)y0f;
    float wx  = p.x - x0f,   wy  = p.y - y0f;
    int   x1  = x0 + 1,      y1  = y0 + 1;

    int x0c = min(max(x0, 0), RESO - 1);
    int x1c = min(max(x1, 0), RESO - 1);
    int y0c = min(max(y0, 0), RESO - 1);
    int y1c = min(max(y1, 0), RESO - 1);

    float vx0 = (x0 >= 0 && x0 < RESO) ? 1.f : 0.f;
    float vx1 = (x1 >= 0 && x1 < RESO) ? 1.f : 0.f;
    float vy0 = (y0 >= 0 && y0 < RESO) ? 1.f : 0.f;
    float vy1 = (y1 >= 0 && y1 < RESO) ? 1.f : 0.f;

    const float2* base = reinterpret_cast<const float2*>(flow) + (size_t)n * RESO * RESO;

    float2 v00 = base[y0c * RESO + x0c];
    float2 v10 = base[y0c * RESO + x1c];
    float2 v01 = base[y1c * RESO + x0c];
    float2 v11 = base[y1c * RESO + x1c];

    float w00 = (1.f - wx) * (1.f - wy) * vx0 * vy0;
    float w10 = wx * (1.f - wy) * vx1 * vy0;
    float w01 = (1.f - wx) * wy * vx0 * vy1;
    float w11 = wx * wy * vx1 * vy1;

    float cx = v00.x * w00 + v10.x * w10 + v01.x * w01 + v11.x * w11;
    float cy = v00.y * w00 + v10.y * w10 + v01.y * w01 + v11.y * w11;

    if (sel) {
        float txe = cx - EPSF, tye = cy - EPSF;
        g_trg4[idx] = make_float4(txe, tye, txe * txe + tye * tye, 0.f);
    } else {
        // pre-scale |s|^2 by log2e^2 so K2's q is in (log2e*dist)^2 units
        g_src4[idx] = make_float4(cx, cy, (cx * cx + cy * cy) * LOG2E2, 0.f);
    }
}

// ---------------------------------------------------------------------------
// Kernel 2 (fused, split-i): block = 128 threads, grid = (K/64, N).
// Threads 0-63 handle j over i in [0,512); threads 64-127 the same j over
// i in [512,1024). Partial sums combined through smem. Doubles resident
// warps (2048 total, ~3.5/SMSP) so the MUFU pipe stays saturated.
// ---------------------------------------------------------------------------
__global__ void __launch_bounds__(128) loss_kernel(const int* __restrict__ kp_vis,
                                                   const float* __restrict__ kp_wt,
                                                   float* __restrict__ out) {
    __shared__ float4 s_src[KK];
    __shared__ float  s_half[64];
    const int n    = blockIdx.y;
    const int tidx = threadIdx.x;
    const int jloc = tidx & 63;
    const int half = tidx >> 6;      // 0: i in [0,512), 1: i in [512,1024)
    const int j    = blockIdx.x * 64 + jloc;

    const float4 t = g_trg4[n * KK + j];

    const float4* srcn = g_src4 + n * KK;
    #pragma unroll
    for (int i = tidx; i < KK; i += 128) s_src[i] = srcn[i];
    __syncthreads();

    // q = log2e^2 * dist^2 = s.z + a*sx + b*sy + ttC2
    const float a    = -2.0f * t.x * LOG2E2;
    const float b    = -2.0f * t.y * LOG2E2;
    const float ttC2 = t.z * LOG2E2;

    const int ibase = half * HALF_I;

    float acc0 = 0.f, acc1 = 0.f, acc2 = 0.f, acc3 = 0.f;
    #pragma unroll 2
    for (int i = 0; i < HALF_I; i += 8) {
        #pragma unroll
        for (int u = 0; u < 8; u += 4) {
            float4 s0 = s_src[ibase + i + u + 0];
            float4 s1 = s_src[ibase + i + u + 1];
            float4 s2 = s_src[ibase + i + u + 2];
            float4 s3 = s_src[ibase + i + u + 3];

            float q0 = fmaf(s0.x, a, fmaf(s0.y, b, s0.z + ttC2));
            float q1 = fmaf(s1.x, a, fmaf(s1.y, b, s1.z + ttC2));
            float q2 = fmaf(s2.x, a, fmaf(s2.y, b, s2.z + ttC2));
            float q3 = fmaf(s3.x, a, fmaf(s3.y, b, s3.z + ttC2));

            float d0 = sqrt_approx(q0);   // = log2e * dist
            float d1 = sqrt_approx(q1);
            float d2 = sqrt_approx(q2);
            float d3 = sqrt_approx(q3);

            acc0 += ex2_approx(-d0);
            acc1 += ex2_approx(-d1);
            acc2 += ex2_approx(-d2);
            acc3 += ex2_approx(-d3);
        }
    }
    float accp = (acc0 + acc1) + (acc2 + acc3);

    // combine the two i-halves
    if (half == 1) s_half[jloc] = accp;
    __syncthreads();

    if (half == 0) {
        float acc = accp + s_half[jloc];

        // diagonal distance (plain units)
        float4 sj = s_src[j];
        float dx = sj.x - t.x, dy = sj.y - t.y;
        float djj = sqrt_approx(fmaf(dy, dy, dx * dx));

        float ce = lg2_approx(acc) * LN2 + djj;

        int   vis = (kp_vis[n * KK + j] != 0);
        float wt  = kp_wt[n * KK + j];
        float contrib = vis ? 2.0f * ce * wt : 0.0f;
        float viscnt  = vis ? 1.0f : 0.0f;

        #pragma unroll
        for (int o = 16; o > 0; o >>= 1) {
            contrib += __shfl_down_sync(0xffffffffu, contrib, o);
            viscnt  += __shfl_down_sync(0xffffffffu, viscnt,  o);
        }
        if ((tidx & 31) == 0) {
            s_half[32 + (tidx >> 5)] = contrib;   // reuse smem slots 32,33
            s_half[40 + (tidx >> 5)] = viscnt;    // slots 40,41
        }
    }
    __syncthreads();
    if (tidx == 0) {
        atomicAdd(&g_loss, (double)(s_half[32] + s_half[33]));
        atomicAdd(&g_vis,  (double)(s_half[40] + s_half[41]));
        __threadfence();
        unsigned int done = atomicAdd(&g_done, 1u);
        if (done == gridDim.x * gridDim.y - 1) {
            double L = atomicAdd(&g_loss, 0.0);
            double V = atomicAdd(&g_vis, 0.0);
            out[0] = (float)(L / V);
        }
    }
}

extern "C" void kernel_launch(void* const* d_in, const int* in_sizes, int n_in,
                              void* d_out, int out_size) {
    const float* src_flow = (const float*)d_in[0];
    const float* trg_flow = (const float*)d_in[1];
    const float* src_kp   = (const float*)d_in[2];
    const float* trg_kp   = (const float*)d_in[3];
    const int*   kp_vis   = (const int*)d_in[4];
    const float* kp_wt    = (const float*)d_in[5];
    float* out = (float*)d_out;

    sample_kernel<<<(2 * NB * KK + 255) / 256, 256>>>(src_flow, trg_flow, src_kp, trg_kp);

    dim3 grid(KK / 64, NB);
    loss_kernel<<<grid, 128>>>(kp_vis, kp_wt, out);
}

// round 8
// speedup vs baseline: 1.1515x; 1.1515x over previous
#include <cuda_runtime.h>
#include <math.h>

#define NB   32
#define RESO 256
#define KK   1024
#define EPSF 1e-6f
#define JCH  32            // j's per block
#define IQ   (KK / 4)      // 256 i's per thread-quarter

// log2(e)^2 and ln(2)
#define LOG2E2  2.0813689810056077f
#define LN2     0.6931471805599453f

// Scratch (no allocations allowed).
// src: (sx, sy, |s|^2 * log2e^2, 0)
// trg: (tx', ty', |t'|^2, 0) with t' = t - eps
__device__ float4 g_src4[NB * KK];
__device__ float4 g_trg4[NB * KK];
__device__ double g_loss;
__device__ double g_vis;
__device__ unsigned int g_done;

__device__ __forceinline__ float sqrt_approx(float x) {
    float r; asm("sqrt.approx.f32 %0, %1;" : "=f"(r) : "f"(x)); return r;
}
__device__ __forceinline__ float ex2_approx(float x) {
    float r; asm("ex2.approx.f32 %0, %1;" : "=f"(r) : "f"(x)); return r;
}
__device__ __forceinline__ float lg2_approx(float x) {
    float r; asm("lg2.approx.f32 %0, %1;" : "=f"(r) : "f"(x)); return r;
}

// ---------------------------------------------------------------------------
// Kernel 1: bilinear sampling; emits packed float4 per point.
// ---------------------------------------------------------------------------
__global__ void sample_kernel(const float* __restrict__ src_flow,
                              const float* __restrict__ trg_flow,
                              const float* __restrict__ src_kp,
                              const float* __restrict__ trg_kp) {
    int tid = blockIdx.x * blockDim.x + threadIdx.x;
    if (tid == 0) { g_loss = 0.0; g_vis = 0.0; g_done = 0u; }
    if (tid >= 2 * NB * KK) return;

    int sel = tid >= NB * KK;          // 0 = src, 1 = trg
    int idx = sel ? (tid - NB * KK) : tid;
    const float* flow = sel ? trg_flow : src_flow;
    const float2 p = reinterpret_cast<const float2*>(sel ? trg_kp : src_kp)[idx];

    int   n = idx / KK;

    float x0f = floorf(p.x), y0f = floorf(p.y);
    int   x0  = (int)x0f,    y0  = (int)y0f;
    float wx  = p.x - x0f,   wy  = p.y - y0f;
    int   x1  = x0 + 1,      y1  = y0 + 1;

    int x0c = min(max(x0, 0), RESO - 1);
    int x1c = min(max(x1, 0), RESO - 1);
    int y0c = min(max(y0, 0), RESO - 1);
    int y1c = min(max(y1, 0), RESO - 1);

    float vx0 = (x0 >= 0 && x0 < RESO) ? 1.f : 0.f;
    float vx1 = (x1 >= 0 && x1 < RESO) ? 1.f : 0.f;
    float vy0 = (y0 >= 0 && y0 < RESO) ? 1.f : 0.f;
    float vy1 = (y1 >= 0 && y1 < RESO) ? 1.f : 0.f;

    const float2* base = reinterpret_cast<const float2*>(flow) + (size_t)n * RESO * RESO;

    float2 v00 = base[y0c * RESO + x0c];
    float2 v10 = base[y0c * RESO + x1c];
    float2 v01 = base[y1c * RESO + x0c];
    float2 v11 = base[y1c * RESO + x1c];

    float w00 = (1.f - wx) * (1.f - wy) * vx0 * vy0;
    float w10 = wx * (1.f - wy) * vx1 * vy0;
    float w01 = (1.f - wx) * wy * vx0 * vy1;
    float w11 = wx * wy * vx1 * vy1;

    float cx = v00.x * w00 + v10.x * w10 + v01.x * w01 + v11.x * w11;
    float cy = v00.y * w00 + v10.y * w10 + v01.y * w01 + v11.y * w11;

    if (sel) {
        float txe = cx - EPSF, tye = cy - EPSF;
        g_trg4[idx] = make_float4(txe, tye, txe * txe + tye * tye, 0.f);
    } else {
        // pre-scale |s|^2 by log2e^2 so K2's q is in (log2e*dist)^2 units
        g_src4[idx] = make_float4(cx, cy, (cx * cx + cy * cy) * LOG2E2, 0.f);
    }
}

// ---------------------------------------------------------------------------
// Kernel 2 (fused, quarter-split): block = 128 threads = 32 j x 4 i-quarters,
// grid = (K/32, N) = 1024 blocks (6.9/SM -> 8% tail instead of 15%).
// 8 independent accumulators per thread; all 1024 i in smem.
// Quarter partials combined through smem; quarter 0 finishes the j.
// ---------------------------------------------------------------------------
__global__ void __launch_bounds__(128, 1) loss_kernel(const int* __restrict__ kp_vis,
                                                      const float* __restrict__ kp_wt,
                                                      float* __restrict__ out) {
    __shared__ float4 s_src[KK];
    __shared__ float  s_part[3 * JCH];
    __shared__ float  s_out[2];

    const int n    = blockIdx.y;
    const int tidx = threadIdx.x;
    const int jloc = tidx & (JCH - 1);
    const int q4   = tidx >> 5;                 // i-quarter 0..3
    const int j    = blockIdx.x * JCH + jloc;

    const float4 t = g_trg4[n * KK + j];

    const float4* srcn = g_src4 + n * KK;
    #pragma unroll
    for (int i = tidx; i < KK; i += 128) s_src[i] = srcn[i];
    __syncthreads();

    // q = log2e^2 * dist^2 = s.z + a*sx + b*sy + ttC2
    const float a    = -2.0f * t.x * LOG2E2;
    const float b    = -2.0f * t.y * LOG2E2;
    const float ttC2 = t.z * LOG2E2;

    const float4* sp = s_src + q4 * IQ;

    float acc[8];
    #pragma unroll
    for (int u = 0; u < 8; u++) acc[u] = 0.f;

    #pragma unroll 2
    for (int i = 0; i < IQ; i += 8) {
        #pragma unroll
        for (int u = 0; u < 8; u++) {
            float4 s = sp[i + u];
            float qv = fmaf(s.x, a, fmaf(s.y, b, s.z + ttC2));
            acc[u] += ex2_approx(-sqrt_approx(qv));   // = exp(-dist)
        }
    }
    float accp = ((acc[0] + acc[1]) + (acc[2] + acc[3]))
               + ((acc[4] + acc[5]) + (acc[6] + acc[7]));

    if (q4 > 0) s_part[(q4 - 1) * JCH + jloc] = accp;
    __syncthreads();

    if (q4 == 0) {
        float accv = accp + s_part[jloc] + s_part[JCH + jloc] + s_part[2 * JCH + jloc];

        // diagonal distance (plain units)
        float4 sj = s_src[j];
        float dx = sj.x - t.x, dy = sj.y - t.y;
        float djj = sqrt_approx(fmaf(dy, dy, dx * dx));

        float ce = lg2_approx(accv) * LN2 + djj;

        int   vis = (kp_vis[n * KK + j] != 0);
        float wt  = kp_wt[n * KK + j];
        float contrib = vis ? 2.0f * ce * wt : 0.0f;
        float viscnt  = vis ? 1.0f : 0.0f;

        #pragma unroll
        for (int o = 16; o > 0; o >>= 1) {
            contrib += __shfl_down_sync(0xffffffffu, contrib, o);
            viscnt  += __shfl_down_sync(0xffffffffu, viscnt,  o);
        }
        if (jloc == 0) { s_out[0] = contrib; s_out[1] = viscnt; }
    }
    __syncthreads();
    if (tidx == 0) {
        atomicAdd(&g_loss, (double)s_out[0]);
        atomicAdd(&g_vis,  (double)s_out[1]);
        __threadfence();
        unsigned int done = atomicAdd(&g_done, 1u);
        if (done == (KK / JCH) * NB - 1) {
            double L = atomicAdd(&g_loss, 0.0);
            double V = atomicAdd(&g_vis, 0.0);
            out[0] = (float)(L / V);
        }
    }
}

extern "C" void kernel_launch(void* const* d_in, const int* in_sizes, int n_in,
                              void* d_out, int out_size) {
    const float* src_flow = (const float*)d_in[0];
    const float* trg_flow = (const float*)d_in[1];
    const float* src_kp   = (const float*)d_in[2];
    const float* trg_kp   = (const float*)d_in[3];
    const int*   kp_vis   = (const int*)d_in[4];
    const float* kp_wt    = (const float*)d_in[5];
    float* out = (float*)d_out;

    sample_kernel<<<(2 * NB * KK + 255) / 256, 256>>>(src_flow, trg_flow, src_kp, trg_kp);

    dim3 grid(KK / JCH, NB);
    loss_kernel<<<grid, 128>>>(kp_vis, kp_wt, out);
}

// round 9
// speedup vs baseline: 1.1633x; 1.0102x over previous
#include <cuda_runtime.h>
#include <math.h>

#define NB   32
#define RESO 256
#define KK   1024
#define EPSF 1e-6f
#define JCH  32            // j's per block
#define NOCT 8             // i-octants (warps) per block
#define IO   (KK / NOCT)   // 128 i's per thread

// log2(e)^2 and ln(2)
#define LOG2E2  2.0813689810056077f
#define LN2     0.6931471805599453f

// Scratch (no allocations allowed).
// src: (sx, sy, |s|^2 * log2e^2, 0)
// trg: (tx', ty', |t'|^2, 0) with t' = t - eps
__device__ float4 g_src4[NB * KK];
__device__ float4 g_trg4[NB * KK];
__device__ double g_loss;
__device__ double g_vis;
__device__ unsigned int g_done;

__device__ __forceinline__ float sqrt_approx(float x) {
    float r; asm("sqrt.approx.f32 %0, %1;" : "=f"(r) : "f"(x)); return r;
}
__device__ __forceinline__ float ex2_approx(float x) {
    float r; asm("ex2.approx.f32 %0, %1;" : "=f"(r) : "f"(x)); return r;
}
__device__ __forceinline__ float lg2_approx(float x) {
    float r; asm("lg2.approx.f32 %0, %1;" : "=f"(r) : "f"(x)); return r;
}

// ---------------------------------------------------------------------------
// Kernel 1: bilinear sampling; emits packed float4 per point.
// ---------------------------------------------------------------------------
__global__ void sample_kernel(const float* __restrict__ src_flow,
                              const float* __restrict__ trg_flow,
                              const float* __restrict__ src_kp,
                              const float* __restrict__ trg_kp) {
    int tid = blockIdx.x * blockDim.x + threadIdx.x;
    if (tid == 0) { g_loss = 0.0; g_vis = 0.0; g_done = 0u; }
    if (tid >= 2 * NB * KK) return;

    int sel = tid >= NB * KK;          // 0 = src, 1 = trg
    int idx = sel ? (tid - NB * KK) : tid;
    const float* flow = sel ? trg_flow : src_flow;
    const float2 p = reinterpret_cast<const float2*>(sel ? trg_kp : src_kp)[idx];

    int   n = idx / KK;

    float x0f = floorf(p.x), y0f = floorf(p.y);
    int   x0  = (int)x0f,    y0  = (int)y0f;
    float wx  = p.x - x0f,   wy  = p.y - y0f;
    int   x1  = x0 + 1,      y1  = y0 + 1;

    int x0c = min(max(x0, 0), RESO - 1);
    int x1c = min(max(x1, 0), RESO - 1);
    int y0c = min(max(y0, 0), RESO - 1);
    int y1c = min(max(y1, 0), RESO - 1);

    float vx0 = (x0 >= 0 && x0 < RESO) ? 1.f : 0.f;
    float vx1 = (x1 >= 0 && x1 < RESO) ? 1.f : 0.f;
    float vy0 = (y0 >= 0 && y0 < RESO) ? 1.f : 0.f;
    float vy1 = (y1 >= 0 && y1 < RESO) ? 1.f : 0.f;

    const float2* base = reinterpret_cast<const float2*>(flow) + (size_t)n * RESO * RESO;

    float2 v00 = base[y0c * RESO + x0c];
    float2 v10 = base[y0c * RESO + x1c];
    float2 v01 = base[y1c * RESO + x0c];
    float2 v11 = base[y1c * RESO + x1c];

    float w00 = (1.f - wx) * (1.f - wy) * vx0 * vy0;
    float w10 = wx * (1.f - wy) * vx1 * vy0;
    float w01 = (1.f - wx) * wy * vx0 * vy1;
    float w11 = wx * wy * vx1 * vy1;

    float cx = v00.x * w00 + v10.x * w10 + v01.x * w01 + v11.x * w11;
    float cy = v00.y * w00 + v10.y * w10 + v01.y * w01 + v11.y * w11;

    if (sel) {
        float txe = cx - EPSF, tye = cy - EPSF;
        g_trg4[idx] = make_float4(txe, tye, txe * txe + tye * tye, 0.f);
    } else {
        // pre-scale |s|^2 by log2e^2 so K2's q is in (log2e*dist)^2 units
        g_src4[idx] = make_float4(cx, cy, (cx * cx + cy * cy) * LOG2E2, 0.f);
    }
}

// ---------------------------------------------------------------------------
// Kernel 2 (fused, octant-split): block = 256 threads = 32 j x 8 i-octants,
// grid = (K/32, N) = 1024 blocks -> ~55 warps/SM so the MUFU pipe stays fed
// through LDS(29cy)/MUFU(16cy) dependency waits.
// Warp k = octant k, lanes = j's (smem reads are broadcast, conflict-free).
// ---------------------------------------------------------------------------
__global__ void __launch_bounds__(256, 1) loss_kernel(const int* __restrict__ kp_vis,
                                                      const float* __restrict__ kp_wt,
                                                      float* __restrict__ out) {
    __shared__ float4 s_src[KK];
    __shared__ float  s_part[(NOCT - 1) * JCH];
    __shared__ float  s_out[2];

    const int n    = blockIdx.y;
    const int tidx = threadIdx.x;
    const int jloc = tidx & (JCH - 1);
    const int oct  = tidx >> 5;                 // i-octant 0..7 (= warp id)
    const int j    = blockIdx.x * JCH + jloc;

    const float4 t = g_trg4[n * KK + j];

    const float4* srcn = g_src4 + n * KK;
    #pragma unroll
    for (int i = tidx; i < KK; i += 256) s_src[i] = srcn[i];
    __syncthreads();

    // q = log2e^2 * dist^2 = s.z + a*sx + b*sy + ttC2
    const float a    = -2.0f * t.x * LOG2E2;
    const float b    = -2.0f * t.y * LOG2E2;
    const float ttC2 = t.z * LOG2E2;

    const float4* sp = s_src + oct * IO;

    float acc[8];
    #pragma unroll
    for (int u = 0; u < 8; u++) acc[u] = 0.f;

    #pragma unroll 2
    for (int i = 0; i < IO; i += 8) {
        #pragma unroll
        for (int u = 0; u < 8; u++) {
            float4 s = sp[i + u];
            float qv = fmaf(s.x, a, fmaf(s.y, b, s.z + ttC2));
            acc[u] += ex2_approx(-sqrt_approx(qv));   // = exp(-dist)
        }
    }
    float accp = ((acc[0] + acc[1]) + (acc[2] + acc[3]))
               + ((acc[4] + acc[5]) + (acc[6] + acc[7]));

    if (oct > 0) s_part[(oct - 1) * JCH + jloc] = accp;
    __syncthreads();

    if (oct == 0) {
        float accv = accp;
        #pragma unroll
        for (int o = 0; o < NOCT - 1; o++) accv += s_part[o * JCH + jloc];

        // diagonal distance (plain units)
        float4 sj = s_src[j];
        float dx = sj.x - t.x, dy = sj.y - t.y;
        float djj = sqrt_approx(fmaf(dy, dy, dx * dx));

        float ce = lg2_approx(accv) * LN2 + djj;

        int   vis = (kp_vis[n * KK + j] != 0);
        float wt  = kp_wt[n * KK + j];
        float contrib = vis ? 2.0f * ce * wt : 0.0f;
        float viscnt  = vis ? 1.0f : 0.0f;

        #pragma unroll
        for (int o = 16; o > 0; o >>= 1) {
            contrib += __shfl_down_sync(0xffffffffu, contrib, o);
            viscnt  += __shfl_down_sync(0xffffffffu, viscnt,  o);
        }
        if (jloc == 0) { s_out[0] = contrib; s_out[1] = viscnt; }
    }
    __syncthreads();
    if (tidx == 0) {
        atomicAdd(&g_loss, (double)s_out[0]);
        atomicAdd(&g_vis,  (double)s_out[1]);
        __threadfence();
        unsigned int done = atomicAdd(&g_done, 1u);
        if (done == (KK / JCH) * NB - 1) {
            double L = atomicAdd(&g_loss, 0.0);
            double V = atomicAdd(&g_vis, 0.0);
            out[0] = (float)(L / V);
        }
    }
}

extern "C" void kernel_launch(void* const* d_in, const int* in_sizes, int n_in,
                              void* d_out, int out_size) {
    const float* src_flow = (const float*)d_in[0];
    const float* trg_flow = (const float*)d_in[1];
    const float* src_kp   = (const float*)d_in[2];
    const float* trg_kp   = (const float*)d_in[3];
    const int*   kp_vis   = (const int*)d_in[4];
    const float* kp_wt    = (const float*)d_in[5];
    float* out = (float*)d_out;

    sample_kernel<<<(2 * NB * KK + 255) / 256, 256>>>(src_flow, trg_flow, src_kp, trg_kp);

    dim3 grid(KK / JCH, NB);
    loss_kernel<<<grid, 256>>>(kp_vis, kp_wt, out);
}

// round 10
// speedup vs baseline: 1.2667x; 1.0889x over previous
#include <cuda_runtime.h>
#include <math.h>

#define NB   32
#define RESO 256
#define KK   1024
#define EPSF 1e-6f
#define JCH  32            // j's per block
#define NOCT 8             // i-octants (warps) per block
#define IO   (KK / NOCT)   // 128 i's per thread

// log2(e)^2 and ln(2)
#define LOG2E2  2.0813689810056077f
#define LN2     0.6931471805599453f

typedef unsigned long long ull;

// Scratch (no allocations allowed).
// src: (sx, sy, |s|^2 * log2e^2, 0)   trg: (tx', ty', |t'|^2, 0), t' = t - eps
__device__ float4 g_src4[NB * KK];
__device__ float4 g_trg4[NB * KK];
__device__ double g_loss;
__device__ double g_vis;
__device__ unsigned int g_done;

__device__ __forceinline__ float rsq_approx(float x) {
    float r; asm("rsqrt.approx.f32 %0, %1;" : "=f"(r) : "f"(x)); return r;
}
__device__ __forceinline__ float sqrt_approx(float x) {
    float r; asm("sqrt.approx.f32 %0, %1;" : "=f"(r) : "f"(x)); return r;
}
__device__ __forceinline__ float ex2_approx(float x) {
    float r; asm("ex2.approx.f32 %0, %1;" : "=f"(r) : "f"(x)); return r;
}
__device__ __forceinline__ float lg2_approx(float x) {
    float r; asm("lg2.approx.f32 %0, %1;" : "=f"(r) : "f"(x)); return r;
}

// packed f32x2 ops (Blackwell; PTX-only)
__device__ __forceinline__ ull fma2(ull a, ull b, ull c) {
    ull r; asm("fma.rn.f32x2 %0, %1, %2, %3;" : "=l"(r) : "l"(a), "l"(b), "l"(c)); return r;
}
__device__ __forceinline__ ull add2(ull a, ull b) {
    ull r; asm("add.rn.f32x2 %0, %1, %2;" : "=l"(r) : "l"(a), "l"(b)); return r;
}
__device__ __forceinline__ ull pack2(float v) {
    ull r; asm("mov.b64 %0, {%1, %1};" : "=l"(r) : "f"(v)); return r;
}
__device__ __forceinline__ void unpack2(ull v, float& lo, float& hi) {
    asm("mov.b64 {%0, %1}, %2;" : "=f"(lo), "=f"(hi) : "l"(v));
}

// ---------------------------------------------------------------------------
// Kernel 1: bilinear sampling; emits packed float4 per point.
// ---------------------------------------------------------------------------
__global__ void sample_kernel(const float* __restrict__ src_flow,
                              const float* __restrict__ trg_flow,
                              const float* __restrict__ src_kp,
                              const float* __restrict__ trg_kp) {
    int tid = blockIdx.x * blockDim.x + threadIdx.x;
    if (tid == 0) { g_loss = 0.0; g_vis = 0.0; g_done = 0u; }
    if (tid >= 2 * NB * KK) return;

    int sel = tid >= NB * KK;          // 0 = src, 1 = trg
    int idx = sel ? (tid - NB * KK) : tid;
    const float* flow = sel ? trg_flow : src_flow;
    const float2 p = reinterpret_cast<const float2*>(sel ? trg_kp : src_kp)[idx];

    int   n = idx / KK;

    float x0f = floorf(p.x), y0f = floorf(p.y);
    int   x0  = (int)x0f,    y0  = (int)y0f;
    float wx  = p.x - x0f,   wy  = p.y - y0f;
    int   x1  = x0 + 1,      y1  = y0 + 1;

    int x0c = min(max(x0, 0), RESO - 1);
    int x1c = min(max(x1, 0), RESO - 1);
    int y0c = min(max(y0, 0), RESO - 1);
    int y1c = min(max(y1, 0), RESO - 1);

    float vx0 = (x0 >= 0 && x0 < RESO) ? 1.f : 0.f;
    float vx1 = (x1 >= 0 && x1 < RESO) ? 1.f : 0.f;
    float vy0 = (y0 >= 0 && y0 < RESO) ? 1.f : 0.f;
    float vy1 = (y1 >= 0 && y1 < RESO) ? 1.f : 0.f;

    const float2* base = reinterpret_cast<const float2*>(flow) + (size_t)n * RESO * RESO;

    float2 v00 = base[y0c * RESO + x0c];
    float2 v10 = base[y0c * RESO + x1c];
    float2 v01 = base[y1c * RESO + x0c];
    float2 v11 = base[y1c * RESO + x1c];

    float w00 = (1.f - wx) * (1.f - wy) * vx0 * vy0;
    float w10 = wx * (1.f - wy) * vx1 * vy0;
    float w01 = (1.f - wx) * wy * vx0 * vy1;
    float w11 = wx * wy * vx1 * vy1;

    float cx = v00.x * w00 + v10.x * w10 + v01.x * w01 + v11.x * w11;
    float cy = v00.y * w00 + v10.y * w10 + v01.y * w01 + v11.y * w11;

    if (sel) {
        float txe = cx - EPSF, tye = cy - EPSF;
        g_trg4[idx] = make_float4(txe, tye, txe * txe + tye * tye, 0.f);
    } else {
        // pre-scale |s|^2 by log2e^2 so K2's q is in (log2e*dist)^2 units
        g_src4[idx] = make_float4(cx, cy, (cx * cx + cy * cy) * LOG2E2, 0.f);
    }
}

// ---------------------------------------------------------------------------
// Kernel 2 (fused, SoA + packed f32x2): block = 256 = 32 j x 8 i-octants,
// grid = (K/32, N) = 1024 blocks.
// Inner loop per pair: 2 MUFU (RSQ, EX2) + 1.5 packed-fma + FMUL(neg-folded)
// + acc FADD + 0.375 LDS.128 -> ~6.5 issue slots inside the 16-cycle MUFU
// envelope per 32 pairs.
// ---------------------------------------------------------------------------
__global__ void __launch_bounds__(256, 1) loss_kernel(const int* __restrict__ kp_vis,
                                                      const float* __restrict__ kp_wt,
                                                      float* __restrict__ out) {
    __shared__ __align__(16) float s_x[KK];
    __shared__ __align__(16) float s_y[KK];
    __shared__ __align__(16) float s_z[KK];
    __shared__ float s_part[(NOCT - 1) * JCH];
    __shared__ float s_out[2];

    const int n    = blockIdx.y;
    const int tidx = threadIdx.x;
    const int jloc = tidx & (JCH - 1);
    const int oct  = tidx >> 5;                 // i-octant 0..7 (= warp id)
    const int j    = blockIdx.x * JCH + jloc;

    const float4 t = g_trg4[n * KK + j];

    const float4* srcn = g_src4 + n * KK;
    #pragma unroll
    for (int i = tidx; i < KK; i += 256) {
        float4 s = srcn[i];
        s_x[i] = s.x; s_y[i] = s.y; s_z[i] = s.z;
    }
    __syncthreads();

    // q = log2e^2 * dist^2 = z + a*x + b*y + ttC2  (z pre-scaled)
    const float af   = -2.0f * t.x * LOG2E2;
    const float bf   = -2.0f * t.y * LOG2E2;
    const float ttC2 = t.z * LOG2E2;
    const ull a2  = pack2(af);
    const ull b2  = pack2(bf);
    const ull tt2 = pack2(ttC2);

    const float* px = s_x + oct * IO;
    const float* py = s_y + oct * IO;
    const float* pz = s_z + oct * IO;

    float acc[8];
    #pragma unroll
    for (int u = 0; u < 8; u++) acc[u] = 0.f;

    #pragma unroll 2
    for (int i = 0; i < IO; i += 8) {
        ulonglong2 xa = *reinterpret_cast<const ulonglong2*>(px + i);
        ulonglong2 xb = *reinterpret_cast<const ulonglong2*>(px + i + 4);
        ulonglong2 ya = *reinterpret_cast<const ulonglong2*>(py + i);
        ulonglong2 yb = *reinterpret_cast<const ulonglong2*>(py + i + 4);
        ulonglong2 za = *reinterpret_cast<const ulonglong2*>(pz + i);
        ulonglong2 zb = *reinterpret_cast<const ulonglong2*>(pz + i + 4);

        ull q01 = fma2(xa.x, a2, fma2(ya.x, b2, add2(za.x, tt2)));
        ull q23 = fma2(xa.y, a2, fma2(ya.y, b2, add2(za.y, tt2)));
        ull q45 = fma2(xb.x, a2, fma2(yb.x, b2, add2(zb.x, tt2)));
        ull q67 = fma2(xb.y, a2, fma2(yb.y, b2, add2(zb.y, tt2)));

        float q0, q1, q2, q3, q4, q5, q6, q7;
        unpack2(q01, q0, q1);
        unpack2(q23, q2, q3);
        unpack2(q45, q4, q5);
        unpack2(q67, q6, q7);

        // exp(-dist) = ex2( -q * rsq(q) );  neg folds into the FMUL operand
        float r0 = rsq_approx(q0);
        float r1 = rsq_approx(q1);
        float r2 = rsq_approx(q2);
        float r3 = rsq_approx(q3);
        float r4 = rsq_approx(q4);
        float r5 = rsq_approx(q5);
        float r6 = rsq_approx(q6);
        float r7 = rsq_approx(q7);

        acc[0] += ex2_approx((-q0) * r0);
        acc[1] += ex2_approx((-q1) * r1);
        acc[2] += ex2_approx((-q2) * r2);
        acc[3] += ex2_approx((-q3) * r3);
        acc[4] += ex2_approx((-q4) * r4);
        acc[5] += ex2_approx((-q5) * r5);
        acc[6] += ex2_approx((-q6) * r6);
        acc[7] += ex2_approx((-q7) * r7);
    }
    float accp = ((acc[0] + acc[1]) + (acc[2] + acc[3]))
               + ((acc[4] + acc[5]) + (acc[6] + acc[7]));

    if (oct > 0) s_part[(oct - 1) * JCH + jloc] = accp;
    __syncthreads();

    if (oct == 0) {
        float accv = accp;
        #pragma unroll
        for (int o = 0; o < NOCT - 1; o++) accv += s_part[o * JCH + jloc];

        // diagonal distance (plain units)
        float dx = s_x[j] - t.x, dy = s_y[j] - t.y;
        float djj = sqrt_approx(fmaf(dy, dy, dx * dx));

        float ce = lg2_approx(accv) * LN2 + djj;

        int   vis = (kp_vis[n * KK + j] != 0);
        float wt  = kp_wt[n * KK + j];
        float contrib = vis ? 2.0f * ce * wt : 0.0f;
        float viscnt  = vis ? 1.0f : 0.0f;

        #pragma unroll
        for (int o = 16; o > 0; o >>= 1) {
            contrib += __shfl_down_sync(0xffffffffu, contrib, o);
            viscnt  += __shfl_down_sync(0xffffffffu, viscnt,  o);
        }
        if (jloc == 0) { s_out[0] = contrib; s_out[1] = viscnt; }
    }
    __syncthreads();
    if (tidx == 0) {
        atomicAdd(&g_loss, (double)s_out[0]);
        atomicAdd(&g_vis,  (double)s_out[1]);
        __threadfence();
        unsigned int done = atomicAdd(&g_done, 1u);
        if (done == (KK / JCH) * NB - 1) {
            double L = atomicAdd(&g_loss, 0.0);
            double V = atomicAdd(&g_vis, 0.0);
            out[0] = (float)(L / V);
        }
    }
}

extern "C" void kernel_launch(void* const* d_in, const int* in_sizes, int n_in,
                              void* d_out, int out_size) {
    const float* src_flow = (const float*)d_in[0];
    const float* trg_flow = (const float*)d_in[1];
    const float* src_kp   = (const float*)d_in[2];
    const float* trg_kp   = (const float*)d_in[3];
    const int*   kp_vis   = (const int*)d_in[4];
    const float* kp_wt    = (const float*)d_in[5];
    float* out = (float*)d_out;

    sample_kernel<<<(2 * NB * KK + 255) / 256, 256>>>(src_flow, trg_flow, src_kp, trg_kp);

    dim3 grid(KK / JCH, NB);
    loss_kernel<<<grid, 256>>>(kp_vis, kp_wt, out);
}